// round 17
// baseline (speedup 1.0000x reference)
#include <cuda_runtime.h>
#include <cuda_bf16.h>
#include <stdint.h>

#define NT 128
#define TILE 128
#define KC 8
#define NCHUNK 4

// Precomputed per-lane B fragments: Bfrag[ks(12)][hl(2)][r(2)][nt(4)][lane(32)]
__device__ unsigned Bfrag_g[12 * 2 * 2 * 4 * 32];

__device__ __forceinline__ float P_val(const float* __restrict__ sig,
                                       const float* __restrict__ W,
                                       int kj, int o) {
    if (o >= 31) return 0.0f;
    int k = kj / 6, j = kj - 6 * k;
    float s = sig[k], s2 = s * s;
    float is2 = 1.0f / (s2 + 1e-6f);
    float is4 = 1.0f / (s2 * s2 + 1e-6f);
    const float* Wk = W + k * 186 + o;          // [k][h][o], H=6, O=31
    if (j == 0) return Wk[0] - is2 * (Wk[93] + Wk[155]);
    if (j == 1) return -is2 * Wk[62];           // * g*dx
    if (j == 2) return -is2 * Wk[31];           // * g*dy
    if (j == 3) return is4 * Wk[155];           // * g*dx^2
    if (j == 4) return is4 * Wk[124];           // * g*dx*dy
    return is4 * Wk[93];                        // * g*dy^2
}

__global__ void hermite_prep(const float* __restrict__ sig,
                             const float* __restrict__ W) {
    int i = blockIdx.x * blockDim.x + threadIdx.x;
    if (i >= 6144) return;
    int lane = i & 31;
    int nt   = (i >> 5) & 3;
    int r    = (i >> 7) & 1;
    int hl   = (i >> 8) & 1;
    int ks   = i >> 9;
    int g = lane >> 2, t = lane & 3;
    int n  = nt * 8 + g;                         // output column o
    int k0 = ks * 16 + r * 8 + 2 * t;            // kj index (k dim of mma)
    float va = P_val(sig, W, k0, n);
    float vb = P_val(sig, W, k0 + 1, n);
    unsigned ua = __float_as_uint(va), ub = __float_as_uint(vb);
    unsigned o32;
    if (hl == 0) {
        o32 = __byte_perm(ua, ub, 0x7632);       // bf16 hi parts, low=k-even
    } else {
        float la = va - __uint_as_float(ua & 0xFFFF0000u);
        float lb = vb - __uint_as_float(ub & 0xFFFF0000u);
        __nv_bfloat162 p = __floats2bfloat162_rn(la, lb);
        o32 = *reinterpret_cast<unsigned*>(&p);
    }
    Bfrag_g[i] = o32;
}

// ---- SMEM layout (words) ----
// dxy : float2[2 bufs][8*128]  @0     -> 4096 words
// gws : float [2 bufs][8*128]  @4096  -> 2048 words
// Thi : 24 x 136               @6144  -> 3264
// Tlo : 24 x 136               @9408  -> 3264
#define DXY_OFF 0
#define GW_OFF  4096
#define T_HI    6144
#define T_LO    (6144 + 3264)
#define SMEM_WORDS (T_LO + 3264)      // 12672 words = 50688 B
#define T_STRIDE 136                   // ≡ 8 (mod 32): LDS.64 conflict-free

extern __shared__ __align__(16) float smem[];

__device__ __forceinline__ void cp8(uint32_t dst, const void* src) {
    asm volatile("cp.async.ca.shared.global [%0], [%1], 8;" :: "r"(dst), "l"(src));
}
__device__ __forceinline__ void cp4(uint32_t dst, const void* src) {
    asm volatile("cp.async.ca.shared.global [%0], [%1], 4;" :: "r"(dst), "l"(src));
}
#define CP_COMMIT() asm volatile("cp.async.commit_group;" ::: "memory")
#define CP_WAIT0()  asm volatile("cp.async.wait_group 0;" ::: "memory")

__device__ __forceinline__ void mma_bf16(float& d0, float& d1, float& d2, float& d3,
                                         unsigned a0, unsigned a1, unsigned a2, unsigned a3,
                                         unsigned b0, unsigned b1) {
    asm volatile(
        "mma.sync.aligned.m16n8k16.row.col.f32.bf16.bf16.f32 "
        "{%0,%1,%2,%3}, {%4,%5,%6,%7}, {%8,%9}, {%0,%1,%2,%3};"
        : "+f"(d0), "+f"(d1), "+f"(d2), "+f"(d3)
        : "r"(a0), "r"(a1), "r"(a2), "r"(a3), "r"(b0), "r"(b1));
}

// interleaved point->column map: (pt, pt+8) become adjacent words
__device__ __forceinline__ int cmap(int pt) {
    return (pt >> 4) * 16 + (pt & 7) * 2 + ((pt >> 3) & 1);
}

__global__ void __launch_bounds__(NT, 4)
hermite_main(const float* __restrict__ mlp,
             const float* __restrict__ cd,
             const float* __restrict__ gw,
             float* __restrict__ out,
             int total) {
    unsigned* Thi = reinterpret_cast<unsigned*>(smem + T_HI);
    unsigned* Tlo = reinterpret_cast<unsigned*>(smem + T_LO);

    const int tid   = threadIdx.x;
    const int wid   = tid >> 5;
    const int lane  = tid & 31;
    const int g     = lane >> 2;
    const int t     = lane & 3;
    const int mw    = wid & 1;        // m half: pts [64mw, 64mw+64)
    const int nw    = wid >> 1;       // n half: outs [16nw, 16nw+16)
    const int tile0 = blockIdx.x * TILE;
    const int ctid  = cmap(tid);      // this thread's T column
    const bool full = (tile0 + TILE <= total);
    const uint32_t smem_b = (uint32_t)__cvta_generic_to_shared(smem);

    // ---- stage raw chunk c into buffer b via cp.async (no registers) ----
#define STAGE_RAW(c, b) do {                                                   \
    _Pragma("unroll")                                                          \
    for (int it = 0; it < 8; it++) {                                           \
        int item = tid + it * NT;                                              \
        int kl   = item & 7;                                                   \
        int pt   = item >> 3;                                                  \
        int k    = (c) * KC + kl;                                              \
        size_t n = (size_t)(tile0 + pt);                                       \
        int col  = pt ^ ((pt & 32) >> 3) ^ (kl << 2);                          \
        int cold = col ^ ((kl >> 2) << 1);                                     \
        uint32_t d8 = smem_b + (DXY_OFF + ((b) * 1024 + kl * 128 + cold) * 2) * 4; \
        uint32_t d4 = smem_b + (GW_OFF + (b) * 1024 + kl * 128 + col) * 4;     \
        if (full) {                                                            \
            cp8(d8, reinterpret_cast<const float2*>(cd) + n * 32 + k);         \
            cp4(d4, gw + n * 32 + k);                                          \
        } else {                                                               \
            float dx = 0.0f, dy = 0.0f, gg = 0.0f;                             \
            if ((int)n < total) {                                              \
                float2 cc = reinterpret_cast<const float2*>(cd)[n * 32 + k];   \
                dx = cc.x; dy = cc.y; gg = gw[n * 32 + k];                     \
            }                                                                  \
            reinterpret_cast<float2*>(smem)[(b) * 1024 + kl * 128 + cold] =    \
                make_float2(dx, dy);                                           \
            smem[GW_OFF + (b) * 1024 + kl * 128 + col] = gg;                   \
        }                                                                      \
    }                                                                          \
    CP_COMMIT();                                                               \
} while (0)

    // ---- monomials from buffer b -> bf16 {hi,lo} into T (thread = pt) ----
#define MONOMIAL(b) do {                                                       \
    const float2* dxy = reinterpret_cast<const float2*>(smem) + (b) * 1024;    \
    const float*  gws = smem + GW_OFF + (b) * 1024;                            \
    _Pragma("unroll")                                                          \
    for (int kl = 0; kl < KC; kl++) {                                          \
        int col  = tid ^ ((tid & 32) >> 3) ^ (kl << 2);                        \
        int cold = col ^ ((kl >> 2) << 1);                                     \
        float2 dd = dxy[kl * 128 + cold];                                      \
        float gg  = gws[kl * 128 + col];                                       \
        float dx = dd.x, dy = dd.y;                                            \
        float m1 = gg * dx, m2 = gg * dy;                                      \
        float m3 = m1 * dx, m4 = m1 * dy, m5 = m2 * dy;                        \
        float pa[3] = { gg, m2, m4 };   /* kj even of each pair */             \
        float pb[3] = { m1, m3, m5 };   /* kj odd */                           \
        _Pragma("unroll")                                                      \
        for (int u = 0; u < 3; u++) {                                          \
            unsigned ua = __float_as_uint(pa[u]);                              \
            unsigned ub = __float_as_uint(pb[u]);                              \
            unsigned hi32 = __byte_perm(ua, ub, 0x7632);                       \
            float la = pa[u] - __uint_as_float(ua & 0xFFFF0000u);              \
            float lb = pb[u] - __uint_as_float(ub & 0xFFFF0000u);              \
            __nv_bfloat162 p = __floats2bfloat162_rn(la, lb);                  \
            int row = 3 * kl + u;                                              \
            Thi[row * T_STRIDE + ctid] = hi32;                                 \
            Tlo[row * T_STRIDE + ctid] = *reinterpret_cast<unsigned*>(&p);     \
        }                                                                      \
    }                                                                          \
} while (0)

    float acc[4][2][4];
#pragma unroll
    for (int mi = 0; mi < 4; mi++)
#pragma unroll
        for (int ni = 0; ni < 2; ni++)
#pragma unroll
            for (int q = 0; q < 4; q++) acc[mi][ni][q] = 0.0f;

    // ---- prologue: chunk 0 staged + converted ----
    STAGE_RAW(0, 0);
    CP_WAIT0();
    __syncthreads();
    MONOMIAL(0);

#pragma unroll 1
    for (int c = 0; c < NCHUNK; c++) {
        if (c + 1 < NCHUNK) STAGE_RAW(c + 1, (c + 1) & 1);  // async, hidden under MMA
        __syncthreads();   // T(c) visible to all warps

        // ---- MMA sweep: 3 k-steps x 4 m-tiles x 2 n-tiles x 3 passes (R13) ----
#pragma unroll
        for (int ksl = 0; ksl < 3; ksl++) {
            int ks = c * 3 + ksl;
            unsigned bh[2][2], bl[2][2];
#pragma unroll
            for (int ni = 0; ni < 2; ni++) {
                int nt = 2 * nw + ni;
#pragma unroll
                for (int r = 0; r < 2; r++) {
                    bh[ni][r] = __ldg(&Bfrag_g[(((ks * 2 + 0) * 2 + r) * 4 + nt) * 32 + lane]);
                    bl[ni][r] = __ldg(&Bfrag_g[(((ks * 2 + 1) * 2 + r) * 4 + nt) * 32 + lane]);
                }
            }
#pragma unroll
            for (int mi = 0; mi < 4; mi++) {
                int c0 = (4 * mw + mi) * 16 + 2 * g;   // {pt0, pt0+8} adjacent
                int rA = (8 * ksl + t) * T_STRIDE;     // pair col t
                int rC = (8 * ksl + t + 4) * T_STRIDE; // pair col t+4 (kj+8)
                uint2 ahA = *reinterpret_cast<const uint2*>(&Thi[rA + c0]);
                uint2 ahC = *reinterpret_cast<const uint2*>(&Thi[rC + c0]);
                uint2 alA = *reinterpret_cast<const uint2*>(&Tlo[rA + c0]);
                uint2 alC = *reinterpret_cast<const uint2*>(&Tlo[rC + c0]);
#pragma unroll
                for (int ni = 0; ni < 2; ni++) {
                    float* d = acc[mi][ni];
                    mma_bf16(d[0], d[1], d[2], d[3], ahA.x, ahA.y, ahC.x, ahC.y,
                             bh[ni][0], bh[ni][1]);
                    mma_bf16(d[0], d[1], d[2], d[3], ahA.x, ahA.y, ahC.x, ahC.y,
                             bl[ni][0], bl[ni][1]);
                    mma_bf16(d[0], d[1], d[2], d[3], alA.x, alA.y, alC.x, alC.y,
                             bh[ni][0], bh[ni][1]);
                }
            }
        }

        if (c + 1 < NCHUNK) {
            CP_WAIT0();        // raw(c+1) landed (overlapped with MMA above)
            __syncthreads();   // MMA(c) T-reads done; raw(c+1) visible to all
            MONOMIAL((c + 1) & 1);
        }
    }
#undef STAGE_RAW
#undef MONOMIAL

    // ---- Epilogue: fragments -> stage[128][33] -> coalesced out = mlp*mix ----
    __syncthreads();
    float* stage = smem;              // 4224 words, reuses dxy/gw region
#pragma unroll
    for (int mi = 0; mi < 4; mi++) {
        int row0 = (4 * mw + mi) * 16 + g;
#pragma unroll
        for (int ni = 0; ni < 2; ni++) {
            int o0 = (2 * nw + ni) * 8 + 2 * t;
            stage[row0 * 33 + o0]           = acc[mi][ni][0];
            stage[row0 * 33 + o0 + 1]       = acc[mi][ni][1];
            stage[(row0 + 8) * 33 + o0]     = acc[mi][ni][2];
            stage[(row0 + 8) * 33 + o0 + 1] = acc[mi][ni][3];
        }
    }
    __syncthreads();

    // incremental rr/o (one division total)
    size_t lim  = (size_t)total * 31;
    size_t base = (size_t)tile0 * 31;
    int rr = tid / 31;
    int o  = tid - rr * 31;
#pragma unroll 1
    for (int e = tid; e < TILE * 31; e += NT) {
        size_t gidx = base + e;
        if (gidx < lim) out[gidx] = mlp[gidx] * stage[rr * 33 + o];
        rr += 4;
        o  += 4;
        if (o >= 31) { o -= 31; rr += 1; }
    }
}

extern "C" void kernel_launch(void* const* d_in, const int* in_sizes, int n_in,
                              void* d_out, int out_size) {
    const float* mlp = (const float*)d_in[0];  // [B,N,31]
    const float* cd  = (const float*)d_in[1];  // [B,N,32,2]
    const float* sig = (const float*)d_in[2];  // [32]
    const float* gw  = (const float*)d_in[3];  // [B,N,32]
    const float* W   = (const float*)d_in[4];  // [32,6,31]

    int total  = in_sizes[3] / 32;             // B*N = 262144
    int blocks = (total + TILE - 1) / TILE;    // 2048

    hermite_prep<<<(6144 + 255) / 256, 256>>>(sig, W);

    cudaFuncSetAttribute(hermite_main,
                         cudaFuncAttributeMaxDynamicSharedMemorySize,
                         SMEM_WORDS * 4);
    hermite_main<<<blocks, NT, SMEM_WORDS * 4>>>(mlp, cd, gw, (float*)d_out, total);
}